// round 3
// baseline (speedup 1.0000x reference)
#include <cuda_runtime.h>
#include <cstdint>

// ---------------------------------------------------------------------------
// VS_LightGCN: 3-layer LightGCN propagation + dot-product readout.
//
//   N = 300000 nodes, D = 64, NNZ = 5e6 edges, ALPHA = 0.5
//   E1 = SpMM(A, cat(user_emb,item_emb)) + 0.5*emb0
//   E2 = SpMM(A, E1) + 0.5*emb0
//   E3 = SpMM(A, E2) + 0.5*emb0
//   light = (cat0 + 3*E1 + 2*E2 + 1*E3) / 4
//   gamma[b] = dot(light[users[b]], light[N_USERS+items[b]])
// ---------------------------------------------------------------------------

#define N_USERS 100000
#define N_ITEMS 200000
#define N_NODES (N_USERS + N_ITEMS)
#define DIM     64
#define DIM4    16   // DIM / 4 float4 chunks per row

// Scratch: three [N, D] fp32 layer buffers (static device globals — no allocs).
__device__ float g_E1[(size_t)N_NODES * DIM];
__device__ float g_E2[(size_t)N_NODES * DIM];
__device__ float g_E3[(size_t)N_NODES * DIM];

// ---------------------------------------------------------------------------
// Init: E1 = E2 = E3 = 0.5 * cat(user_emb0, item_emb0)
// One float4 chunk per thread.
// ---------------------------------------------------------------------------
__global__ void lgcn_init_kernel(const float4* __restrict__ u0,
                                 const float4* __restrict__ i0)
{
    int j = blockIdx.x * blockDim.x + threadIdx.x;     // chunk index over N*DIM4
    const int total = N_NODES * DIM4;
    if (j >= total) return;

    int n = j >> 4;  // node  (DIM4 == 16)
    float4 v;
    if (n < N_USERS) {
        v = u0[j];
    } else {
        v = i0[j - N_USERS * DIM4];
    }
    v.x *= 0.5f; v.y *= 0.5f; v.z *= 0.5f; v.w *= 0.5f;

    float4* e1 = reinterpret_cast<float4*>(g_E1);
    float4* e2 = reinterpret_cast<float4*>(g_E2);
    float4* e3 = reinterpret_cast<float4*>(g_E3);
    e1[j] = v;
    e2[j] = v;
    e3[j] = v;
}

// ---------------------------------------------------------------------------
// SpMM (edge-parallel, vectorized atomic reduction):
//   out[rows[e]] += vals[e] * in[cols[e]]
// 16 threads per edge; each thread handles one float4 chunk:
//   one LDG.128 gather + one red.global.add.v4.f32 (sm_90+).
// layer selects input/output buffers inside device code (no symbol lookup).
// ---------------------------------------------------------------------------
__global__ void lgcn_spmm_kernel(const int*   __restrict__ rows,
                                 const int*   __restrict__ cols,
                                 const float* __restrict__ vals,
                                 int nnz,
                                 const float4* __restrict__ user_emb4,
                                 const float4* __restrict__ item_emb4,
                                 int layer)
{
    int idx = blockIdx.x * blockDim.x + threadIdx.x;   // up to nnz*16 = 80M < 2^31
    int e = idx >> 4;
    if (e >= nnz) return;
    int c = idx & 15;

    int   r   = __ldg(rows + e);
    int   col = __ldg(cols + e);
    float v   = __ldg(vals + e);

    // Select input (split concat for layer 0) and output buffers.
    float4 g;
    float4* out;
    if (layer == 0) {
        g = (col < N_USERS) ? user_emb4[col * DIM4 + c]
                            : item_emb4[(col - N_USERS) * DIM4 + c];
        out = reinterpret_cast<float4*>(g_E1);
    } else if (layer == 1) {
        g   = reinterpret_cast<const float4*>(g_E1)[col * DIM4 + c];
        out = reinterpret_cast<float4*>(g_E2);
    } else {
        g   = reinterpret_cast<const float4*>(g_E2)[col * DIM4 + c];
        out = reinterpret_cast<float4*>(g_E3);
    }

    float4* p = out + (size_t)r * DIM4 + c;
    float ax = g.x * v, ay = g.y * v, az = g.z * v, aw = g.w * v;
    asm volatile("red.global.add.v4.f32 [%0], {%1, %2, %3, %4};"
                 :: "l"(p), "f"(ax), "f"(ay), "f"(az), "f"(aw)
                 : "memory");
}

// ---------------------------------------------------------------------------
// Epilogue: one warp per output b.
//   light[n,d] = (cat0[n,d] + 3*E1 + 2*E2 + E3) * 0.25
//   gamma[b]   = sum_d light[u,d] * light[i,d]
// Each lane covers dims d and d+32, then warp-reduces.
// ---------------------------------------------------------------------------
__global__ void lgcn_epilogue_kernel(const int* __restrict__ users,
                                     const int* __restrict__ items,
                                     const float* __restrict__ user_emb,
                                     const float* __restrict__ item_emb,
                                     float* __restrict__ out,
                                     int B)
{
    int t = blockIdx.x * blockDim.x + threadIdx.x;
    int b = t >> 5;
    int lane = t & 31;
    if (b >= B) return;

    int u = __ldg(users + b);             // in [0, N_USERS)
    int i = N_USERS + __ldg(items + b);   // in [N_USERS, N)

    float s = 0.0f;
#pragma unroll
    for (int k = 0; k < 2; k++) {
        int d = lane + 32 * k;
        size_t uo = (size_t)u * DIM + d;
        size_t io = (size_t)i * DIM + d;

        float cu = (u < N_USERS) ? user_emb[uo]
                                 : item_emb[(size_t)(u - N_USERS) * DIM + d];
        float ci = item_emb[(size_t)(i - N_USERS) * DIM + d];

        float lu = (cu + 3.0f * g_E1[uo] + 2.0f * g_E2[uo] + g_E3[uo]) * 0.25f;
        float li = (ci + 3.0f * g_E1[io] + 2.0f * g_E2[io] + g_E3[io]) * 0.25f;
        s += lu * li;
    }
#pragma unroll
    for (int o = 16; o > 0; o >>= 1)
        s += __shfl_xor_sync(0xffffffffu, s, o);
    if (lane == 0) out[b] = s;
}

// ---------------------------------------------------------------------------
// kernel_launch: 5 stream-ordered kernel launches. Graph-capturable:
// no syncs, no allocations, no memcpys.
// Input order (metadata): users, items, rows, cols, vals,
//                         user_emb, item_emb, user_emb0, item_emb0
// ---------------------------------------------------------------------------
extern "C" void kernel_launch(void* const* d_in, const int* in_sizes, int n_in,
                              void* d_out, int out_size)
{
    const int*   users     = (const int*)  d_in[0];
    const int*   items     = (const int*)  d_in[1];
    const int*   rows      = (const int*)  d_in[2];
    const int*   cols      = (const int*)  d_in[3];
    const float* vals      = (const float*)d_in[4];
    const float* user_emb  = (const float*)d_in[5];
    const float* item_emb  = (const float*)d_in[6];
    const float* user_emb0 = (const float*)d_in[7];
    const float* item_emb0 = (const float*)d_in[8];
    float*       out       = (float*)d_out;

    const int nnz = in_sizes[2];
    const int B   = in_sizes[0];

    // 1) E1/E2/E3 := 0.5 * emb0  (folds the ALPHA residual into init)
    {
        int total = N_NODES * DIM4;
        int threads = 256;
        int blocks = (total + threads - 1) / threads;
        lgcn_init_kernel<<<blocks, threads>>>(
            (const float4*)user_emb0, (const float4*)item_emb0);
    }

    // 2) Three SpMM layers (atomic accumulate on top of the init)
    {
        int threads = 256;
        long long work = (long long)nnz * DIM4;
        int blocks = (int)((work + threads - 1) / threads);
        lgcn_spmm_kernel<<<blocks, threads>>>(rows, cols, vals, nnz,
                                              (const float4*)user_emb,
                                              (const float4*)item_emb, 0);
        lgcn_spmm_kernel<<<blocks, threads>>>(rows, cols, vals, nnz,
                                              (const float4*)user_emb,
                                              (const float4*)item_emb, 1);
        lgcn_spmm_kernel<<<blocks, threads>>>(rows, cols, vals, nnz,
                                              (const float4*)user_emb,
                                              (const float4*)item_emb, 2);
    }

    // 3) Readout: gamma[b] = <light[u], light[i]>
    {
        int threads = 256;
        int blocks = (B * 32 + threads - 1) / threads;
        lgcn_epilogue_kernel<<<blocks, threads>>>(users, items,
                                                  user_emb, item_emb, out, B);
    }
}

// round 5
// speedup vs baseline: 2.1203x; 2.1203x over previous
#include <cuda_runtime.h>
#include <cstdint>

// ---------------------------------------------------------------------------
// VS_LightGCN: 3-layer LightGCN propagation + dot-product readout.
//   N = 300000, D = 64, NNZ = 5e6, ALPHA = 0.5
//   Ek = SpMM(A, E_{k-1}) + 0.5*emb0     (E0 = cat(user_emb, item_emb))
//   light = (E0 + 3E1 + 2E2 + E3)/4 ;  gamma[b] = <light[u], light[N_USERS+i]>
//
// R3 strategy: build CSR per call (histogram + deterministic scan + scatter),
// then atomic-free row-parallel SpMM (warp per row, register accumulation).
// ---------------------------------------------------------------------------

#define N_USERS 100000
#define N_ITEMS 200000
#define N_NODES (N_USERS + N_ITEMS)
#define DIM     64
#define DIM2    32           // float2 chunks per row
#define NNZ_MAX 5000000

#define SCAN_THREADS 512
#define SCAN_ITEMS   4
#define SCAN_CHUNK   (SCAN_THREADS * SCAN_ITEMS)      // 2048
#define SCAN_NBLK    ((N_NODES + SCAN_CHUNK - 1) / SCAN_CHUNK)  // 147

// ---- static device scratch (no allocations allowed) -----------------------
__device__ float g_E1[(size_t)N_NODES * DIM];
__device__ float g_E2[(size_t)N_NODES * DIM];
__device__ float g_E3[(size_t)N_NODES * DIM];
__device__ int   g_cnt[N_NODES];
__device__ int   g_rowptr[N_NODES + 1];
__device__ int   g_cursor[N_NODES];
__device__ int   g_bsum[SCAN_NBLK];
__device__ int   g_bbase[SCAN_NBLK];
__device__ int2  g_edge[NNZ_MAX];      // packed {col, bits(val)}

// ---------------------------------------------------------------------------
// 1) zero row counts
// ---------------------------------------------------------------------------
__global__ void k_zero_cnt()
{
    int i = blockIdx.x * blockDim.x + threadIdx.x;
    if (i < N_NODES) g_cnt[i] = 0;
}

// ---------------------------------------------------------------------------
// 2) histogram of destination rows
// ---------------------------------------------------------------------------
__global__ void k_hist(const int* __restrict__ rows, int nnz)
{
    int e = blockIdx.x * blockDim.x + threadIdx.x;
    if (e < nnz) atomicAdd(&g_cnt[rows[e]], 1);
}

// ---------------------------------------------------------------------------
// 3a) per-block sums of counts
// ---------------------------------------------------------------------------
__global__ void k_scan_sums()
{
    __shared__ int warp_sums[SCAN_THREADS / 32];
    int i0 = blockIdx.x * SCAN_CHUNK + threadIdx.x * SCAN_ITEMS;
    int t = 0;
#pragma unroll
    for (int k = 0; k < SCAN_ITEMS; k++) {
        int i = i0 + k;
        t += (i < N_NODES) ? g_cnt[i] : 0;
    }
    // warp reduce
#pragma unroll
    for (int o = 16; o > 0; o >>= 1) t += __shfl_xor_sync(0xffffffffu, t, o);
    int lane = threadIdx.x & 31, wid = threadIdx.x >> 5;
    if (lane == 0) warp_sums[wid] = t;
    __syncthreads();
    if (threadIdx.x == 0) {
        int s = 0;
#pragma unroll
        for (int w = 0; w < SCAN_THREADS / 32; w++) s += warp_sums[w];
        g_bsum[blockIdx.x] = s;
    }
}

// ---------------------------------------------------------------------------
// 3b) serial scan over block sums (147 entries — negligible)
// ---------------------------------------------------------------------------
__global__ void k_scan_top(int nnz)
{
    if (threadIdx.x == 0) {
        int acc = 0;
        for (int b = 0; b < SCAN_NBLK; b++) {
            g_bbase[b] = acc;
            acc += g_bsum[b];
        }
        g_rowptr[N_NODES] = nnz;
    }
}

// ---------------------------------------------------------------------------
// 3c) block-local exclusive scan + base -> rowptr & cursor
// ---------------------------------------------------------------------------
__global__ void k_scan_final()
{
    __shared__ int warp_sums[SCAN_THREADS / 32];
    int lane = threadIdx.x & 31, wid = threadIdx.x >> 5;
    int i0 = blockIdx.x * SCAN_CHUNK + threadIdx.x * SCAN_ITEMS;

    int c[SCAN_ITEMS];
    int t = 0;
#pragma unroll
    for (int k = 0; k < SCAN_ITEMS; k++) {
        int i = i0 + k;
        c[k] = (i < N_NODES) ? g_cnt[i] : 0;
        t += c[k];
    }
    // warp inclusive scan of per-thread totals
    int incl = t;
#pragma unroll
    for (int o = 1; o < 32; o <<= 1) {
        int v = __shfl_up_sync(0xffffffffu, incl, o);
        if (lane >= o) incl += v;
    }
    if (lane == 31) warp_sums[wid] = incl;
    __syncthreads();
    if (wid == 0) {
        int v = (lane < SCAN_THREADS / 32) ? warp_sums[lane] : 0;
#pragma unroll
        for (int o = 1; o < SCAN_THREADS / 32; o <<= 1) {
            int u = __shfl_up_sync(0xffffffffu, v, o);
            if (lane >= o) v += u;
        }
        if (lane < SCAN_THREADS / 32) warp_sums[lane] = v;  // inclusive
    }
    __syncthreads();
    int warp_excl = (wid == 0) ? 0 : warp_sums[wid - 1];
    int ex = g_bbase[blockIdx.x] + warp_excl + (incl - t);
#pragma unroll
    for (int k = 0; k < SCAN_ITEMS; k++) {
        int i = i0 + k;
        if (i < N_NODES) {
            g_rowptr[i] = ex;
            g_cursor[i] = ex;
            ex += c[k];
        }
    }
}

// ---------------------------------------------------------------------------
// 4) scatter edges into CSR slots (packed col+val, one STG.64)
// ---------------------------------------------------------------------------
__global__ void k_scatter(const int*   __restrict__ rows,
                          const int*   __restrict__ cols,
                          const float* __restrict__ vals, int nnz)
{
    int e = blockIdx.x * blockDim.x + threadIdx.x;
    if (e >= nnz) return;
    int r = rows[e];
    int pos = atomicAdd(&g_cursor[r], 1);
    g_edge[pos] = make_int2(cols[e], __float_as_int(vals[e]));
}

// ---------------------------------------------------------------------------
// 5) Row-parallel SpMM: one warp per row, lane owns one float2 of D.
//    acc = 0.5*emb0[row] + sum_j val_j * in[col_j]   -> one streamed store.
// ---------------------------------------------------------------------------
template <int LAYER>
__global__ void __launch_bounds__(256)
k_spmm_csr(const float2* __restrict__ user_emb,
           const float2* __restrict__ item_emb,
           const float2* __restrict__ user_emb0,
           const float2* __restrict__ item_emb0)
{
    int w    = (blockIdx.x * blockDim.x + threadIdx.x) >> 5;
    int lane = threadIdx.x & 31;
    if (w >= N_NODES) return;
    int row = w;

    int start = __ldg(&g_rowptr[row]);
    int end   = __ldg(&g_rowptr[row + 1]);

    float2 r0 = (row < N_USERS) ? __ldg(&user_emb0[row * DIM2 + lane])
                                : __ldg(&item_emb0[(row - N_USERS) * DIM2 + lane]);
    float2 acc;
    acc.x = 0.5f * r0.x;
    acc.y = 0.5f * r0.y;

    const float2* E1 = reinterpret_cast<const float2*>(g_E1);
    const float2* E2 = reinterpret_cast<const float2*>(g_E2);

    // software-pipelined edge stream (broadcast load, all lanes same addr)
    int2 ev = (start < end) ? __ldg(&g_edge[start]) : make_int2(0, 0);
    for (int j = start; j < end; j++) {
        int2 cur = ev;
        if (j + 1 < end) ev = __ldg(&g_edge[j + 1]);
        int   c = cur.x;
        float v = __int_as_float(cur.y);

        float2 g;
        if (LAYER == 0) {
            g = (c < N_USERS) ? __ldg(&user_emb[c * DIM2 + lane])
                              : __ldg(&item_emb[(c - N_USERS) * DIM2 + lane]);
        } else if (LAYER == 1) {
            g = __ldg(&E1[c * DIM2 + lane]);
        } else {
            g = __ldg(&E2[c * DIM2 + lane]);
        }
        acc.x = fmaf(v, g.x, acc.x);
        acc.y = fmaf(v, g.y, acc.y);
    }

    float2* out = reinterpret_cast<float2*>(
        (LAYER == 0) ? g_E1 : (LAYER == 1) ? g_E2 : g_E3);
    out[row * DIM2 + lane] = acc;
}

// ---------------------------------------------------------------------------
// 6) Epilogue: warp per output b.
//    light[n,d] = (E0 + 3E1 + 2E2 + E3) * 0.25 ; gamma = dot over D
// ---------------------------------------------------------------------------
__global__ void k_epilogue(const int* __restrict__ users,
                           const int* __restrict__ items,
                           const float* __restrict__ user_emb,
                           const float* __restrict__ item_emb,
                           float* __restrict__ out, int B)
{
    int t = blockIdx.x * blockDim.x + threadIdx.x;
    int b = t >> 5;
    int lane = t & 31;
    if (b >= B) return;

    int u = __ldg(users + b);
    int i = N_USERS + __ldg(items + b);

    float s = 0.0f;
#pragma unroll
    for (int k = 0; k < 2; k++) {
        int d = lane + 32 * k;
        size_t uo = (size_t)u * DIM + d;
        size_t io = (size_t)i * DIM + d;

        float cu = user_emb[uo];  // u always < N_USERS
        float ci = item_emb[(size_t)(i - N_USERS) * DIM + d];

        float lu = (cu + 3.0f * g_E1[uo] + 2.0f * g_E2[uo] + g_E3[uo]) * 0.25f;
        float li = (ci + 3.0f * g_E1[io] + 2.0f * g_E2[io] + g_E3[io]) * 0.25f;
        s = fmaf(lu, li, s);
    }
#pragma unroll
    for (int o = 16; o > 0; o >>= 1)
        s += __shfl_xor_sync(0xffffffffu, s, o);
    if (lane == 0) out[b] = s;
}

// ---------------------------------------------------------------------------
// kernel_launch — stream-ordered, graph-capturable, allocation-free.
// Inputs: users, items, rows, cols, vals, user_emb, item_emb, user_emb0, item_emb0
// ---------------------------------------------------------------------------
extern "C" void kernel_launch(void* const* d_in, const int* in_sizes, int n_in,
                              void* d_out, int out_size)
{
    const int*   users     = (const int*)  d_in[0];
    const int*   items     = (const int*)  d_in[1];
    const int*   rows      = (const int*)  d_in[2];
    const int*   cols      = (const int*)  d_in[3];
    const float* vals      = (const float*)d_in[4];
    const float* user_emb  = (const float*)d_in[5];
    const float* item_emb  = (const float*)d_in[6];
    const float* user_emb0 = (const float*)d_in[7];
    const float* item_emb0 = (const float*)d_in[8];
    float*       out       = (float*)d_out;

    const int nnz = in_sizes[2];
    const int B   = in_sizes[0];

    // --- CSR build ---
    k_zero_cnt<<<(N_NODES + 255) / 256, 256>>>();
    k_hist<<<(nnz + 255) / 256, 256>>>(rows, nnz);
    k_scan_sums<<<SCAN_NBLK, SCAN_THREADS>>>();
    k_scan_top<<<1, 32>>>(nnz);
    k_scan_final<<<SCAN_NBLK, SCAN_THREADS>>>();
    k_scatter<<<(nnz + 255) / 256, 256>>>(rows, cols, vals, nnz);

    // --- 3 propagation layers (warp per row, 8 warps/block) ---
    int spmm_blocks = (N_NODES + 7) / 8;
    k_spmm_csr<0><<<spmm_blocks, 256>>>((const float2*)user_emb,
                                        (const float2*)item_emb,
                                        (const float2*)user_emb0,
                                        (const float2*)item_emb0);
    k_spmm_csr<1><<<spmm_blocks, 256>>>((const float2*)user_emb,
                                        (const float2*)item_emb,
                                        (const float2*)user_emb0,
                                        (const float2*)item_emb0);
    k_spmm_csr<2><<<spmm_blocks, 256>>>((const float2*)user_emb,
                                        (const float2*)item_emb,
                                        (const float2*)user_emb0,
                                        (const float2*)item_emb0);

    // --- readout ---
    k_epilogue<<<(B * 32 + 255) / 256, 256>>>(users, items, user_emb, item_emb,
                                              out, B);
}

// round 6
// speedup vs baseline: 2.9823x; 1.4066x over previous
#include <cuda_runtime.h>
#include <cstdint>

// ---------------------------------------------------------------------------
// VS_LightGCN: 3-layer LightGCN propagation + dot-product readout.
//   N = 300000, D = 64, NNZ = 5e6, ALPHA = 0.5
//   Ek = SpMM(A, E_{k-1}) + 0.5*emb0     (E0 = cat(user_emb, item_emb))
//   light = (E0 + 3E1 + 2E2 + E3)/4 ;  gamma[b] = <light[u], light[N_USERS+i]>
//
// R6: output-sparsity pruning. Only ~8.1K rows of E3 and ~112K rows of E2 are
// ever read downstream; flag them and skip the rest in the SpMM layers.
// ---------------------------------------------------------------------------

#define N_USERS 100000
#define N_ITEMS 200000
#define N_NODES (N_USERS + N_ITEMS)
#define DIM     64
#define DIM2    32           // float2 chunks per row
#define NNZ_MAX 5000000

#define SCAN_THREADS 512
#define SCAN_ITEMS   4
#define SCAN_CHUNK   (SCAN_THREADS * SCAN_ITEMS)                // 2048
#define SCAN_NBLK    ((N_NODES + SCAN_CHUNK - 1) / SCAN_CHUNK)  // 147

// ---- static device scratch (no allocations allowed) -----------------------
__device__ float g_E1[(size_t)N_NODES * DIM];
__device__ float g_E2[(size_t)N_NODES * DIM];
__device__ float g_E3[(size_t)N_NODES * DIM];
__device__ int   g_cnt[N_NODES];
__device__ int   g_rowptr[N_NODES + 1];
__device__ int   g_cursor[N_NODES];
__device__ int   g_bsum[SCAN_NBLK];
__device__ int   g_bbase[SCAN_NBLK];
__device__ int2  g_edge[NNZ_MAX];              // packed {col, bits(val)}
__device__ unsigned char g_flag2[N_NODES];     // rows of E2 that must be computed
__device__ unsigned char g_flag3[N_NODES];     // rows of E3 that must be computed

// ---------------------------------------------------------------------------
// 1) zero counts + flags
// ---------------------------------------------------------------------------
__global__ void k_zero()
{
    int i = blockIdx.x * blockDim.x + threadIdx.x;
    if (i < N_NODES) {
        g_cnt[i]   = 0;
        g_flag2[i] = 0;
        g_flag3[i] = 0;
    }
}

// ---------------------------------------------------------------------------
// 1b) mark query nodes: flag3 (E3 rows) and flag2 (E2 also read at queries)
// ---------------------------------------------------------------------------
__global__ void k_mark_queries(const int* __restrict__ users,
                               const int* __restrict__ items, int B)
{
    int b = blockIdx.x * blockDim.x + threadIdx.x;
    if (b >= B) return;
    int u = users[b];
    int i = N_USERS + items[b];
    g_flag3[u] = 1;  g_flag2[u] = 1;
    g_flag3[i] = 1;  g_flag2[i] = 1;
}

// ---------------------------------------------------------------------------
// 2) histogram of destination rows
// ---------------------------------------------------------------------------
__global__ void k_hist(const int* __restrict__ rows, int nnz)
{
    int e = blockIdx.x * blockDim.x + threadIdx.x;
    if (e < nnz) atomicAdd(&g_cnt[rows[e]], 1);
}

// ---------------------------------------------------------------------------
// 3a) per-block sums of counts
// ---------------------------------------------------------------------------
__global__ void k_scan_sums()
{
    __shared__ int warp_sums[SCAN_THREADS / 32];
    int i0 = blockIdx.x * SCAN_CHUNK + threadIdx.x * SCAN_ITEMS;
    int t = 0;
#pragma unroll
    for (int k = 0; k < SCAN_ITEMS; k++) {
        int i = i0 + k;
        t += (i < N_NODES) ? g_cnt[i] : 0;
    }
#pragma unroll
    for (int o = 16; o > 0; o >>= 1) t += __shfl_xor_sync(0xffffffffu, t, o);
    int lane = threadIdx.x & 31, wid = threadIdx.x >> 5;
    if (lane == 0) warp_sums[wid] = t;
    __syncthreads();
    if (threadIdx.x == 0) {
        int s = 0;
#pragma unroll
        for (int w = 0; w < SCAN_THREADS / 32; w++) s += warp_sums[w];
        g_bsum[blockIdx.x] = s;
    }
}

// ---------------------------------------------------------------------------
// 3b) parallel scan over the 147 block sums (one 256-thread block)
// ---------------------------------------------------------------------------
__global__ void k_scan_top(int nnz)
{
    __shared__ int sh[256];
    int i = threadIdx.x;
    int v = (i < SCAN_NBLK) ? g_bsum[i] : 0;
    sh[i] = v;
    __syncthreads();
#pragma unroll
    for (int o = 1; o < 256; o <<= 1) {
        int t = (i >= o) ? sh[i - o] : 0;
        __syncthreads();
        sh[i] += t;
        __syncthreads();
    }
    if (i < SCAN_NBLK) g_bbase[i] = sh[i] - v;   // exclusive
    if (i == 0) g_rowptr[N_NODES] = nnz;
}

// ---------------------------------------------------------------------------
// 3c) block-local exclusive scan + base -> rowptr & cursor
// ---------------------------------------------------------------------------
__global__ void k_scan_final()
{
    __shared__ int warp_sums[SCAN_THREADS / 32];
    int lane = threadIdx.x & 31, wid = threadIdx.x >> 5;
    int i0 = blockIdx.x * SCAN_CHUNK + threadIdx.x * SCAN_ITEMS;

    int c[SCAN_ITEMS];
    int t = 0;
#pragma unroll
    for (int k = 0; k < SCAN_ITEMS; k++) {
        int i = i0 + k;
        c[k] = (i < N_NODES) ? g_cnt[i] : 0;
        t += c[k];
    }
    int incl = t;
#pragma unroll
    for (int o = 1; o < 32; o <<= 1) {
        int v = __shfl_up_sync(0xffffffffu, incl, o);
        if (lane >= o) incl += v;
    }
    if (lane == 31) warp_sums[wid] = incl;
    __syncthreads();
    if (wid == 0) {
        int v = (lane < SCAN_THREADS / 32) ? warp_sums[lane] : 0;
#pragma unroll
        for (int o = 1; o < SCAN_THREADS / 32; o <<= 1) {
            int u = __shfl_up_sync(0xffffffffu, v, o);
            if (lane >= o) v += u;
        }
        if (lane < SCAN_THREADS / 32) warp_sums[lane] = v;
    }
    __syncthreads();
    int warp_excl = (wid == 0) ? 0 : warp_sums[wid - 1];
    int ex = g_bbase[blockIdx.x] + warp_excl + (incl - t);
#pragma unroll
    for (int k = 0; k < SCAN_ITEMS; k++) {
        int i = i0 + k;
        if (i < N_NODES) {
            g_rowptr[i] = ex;
            g_cursor[i] = ex;
            ex += c[k];
        }
    }
}

// ---------------------------------------------------------------------------
// 4) scatter edges into CSR slots + propagate flag3 -> flag2 over edges
//    (flag2[col] needed whenever col feeds a flagged E3 row)
// ---------------------------------------------------------------------------
__global__ void k_scatter(const int*   __restrict__ rows,
                          const int*   __restrict__ cols,
                          const float* __restrict__ vals, int nnz)
{
    int e = blockIdx.x * blockDim.x + threadIdx.x;
    if (e >= nnz) return;
    int r = rows[e];
    int c = cols[e];
    int pos = atomicAdd(&g_cursor[r], 1);
    g_edge[pos] = make_int2(c, __float_as_int(vals[e]));
    if (g_flag3[r]) g_flag2[c] = 1;
}

// ---------------------------------------------------------------------------
// 5) Row-parallel SpMM: one warp per row, lane owns one float2 of D.
//    LAYER 0 -> E1 (all rows), LAYER 1 -> E2 (flag2 rows), LAYER 2 -> E3
//    (flag3 rows). acc = 0.5*emb0[row] + sum_j val_j * in[col_j].
// ---------------------------------------------------------------------------
template <int LAYER>
__global__ void __launch_bounds__(256)
k_spmm_csr(const float2* __restrict__ user_emb,
           const float2* __restrict__ item_emb,
           const float2* __restrict__ user_emb0,
           const float2* __restrict__ item_emb0)
{
    int w    = (blockIdx.x * blockDim.x + threadIdx.x) >> 5;
    int lane = threadIdx.x & 31;
    if (w >= N_NODES) return;
    int row = w;

    if (LAYER == 1 && !g_flag2[row]) return;   // E2 row never read downstream
    if (LAYER == 2 && !g_flag3[row]) return;   // E3 row never read downstream

    int start = __ldg(&g_rowptr[row]);
    int end   = __ldg(&g_rowptr[row + 1]);

    float2 r0 = (row < N_USERS) ? __ldg(&user_emb0[row * DIM2 + lane])
                                : __ldg(&item_emb0[(row - N_USERS) * DIM2 + lane]);
    float2 acc;
    acc.x = 0.5f * r0.x;
    acc.y = 0.5f * r0.y;

    const float2* E1 = reinterpret_cast<const float2*>(g_E1);
    const float2* E2 = reinterpret_cast<const float2*>(g_E2);

    int2 ev = (start < end) ? __ldg(&g_edge[start]) : make_int2(0, 0);
    for (int j = start; j < end; j++) {
        int2 cur = ev;
        if (j + 1 < end) ev = __ldg(&g_edge[j + 1]);
        int   c = cur.x;
        float v = __int_as_float(cur.y);

        float2 g;
        if (LAYER == 0) {
            g = (c < N_USERS) ? __ldg(&user_emb[c * DIM2 + lane])
                              : __ldg(&item_emb[(c - N_USERS) * DIM2 + lane]);
        } else if (LAYER == 1) {
            g = __ldg(&E1[c * DIM2 + lane]);
        } else {
            g = __ldg(&E2[c * DIM2 + lane]);
        }
        acc.x = fmaf(v, g.x, acc.x);
        acc.y = fmaf(v, g.y, acc.y);
    }

    float2* out = reinterpret_cast<float2*>(
        (LAYER == 0) ? g_E1 : (LAYER == 1) ? g_E2 : g_E3);
    out[row * DIM2 + lane] = acc;
}

// ---------------------------------------------------------------------------
// 6) Epilogue: warp per output b.
// ---------------------------------------------------------------------------
__global__ void k_epilogue(const int* __restrict__ users,
                           const int* __restrict__ items,
                           const float* __restrict__ user_emb,
                           const float* __restrict__ item_emb,
                           float* __restrict__ out, int B)
{
    int t = blockIdx.x * blockDim.x + threadIdx.x;
    int b = t >> 5;
    int lane = t & 31;
    if (b >= B) return;

    int u = __ldg(users + b);
    int i = N_USERS + __ldg(items + b);

    float s = 0.0f;
#pragma unroll
    for (int k = 0; k < 2; k++) {
        int d = lane + 32 * k;
        size_t uo = (size_t)u * DIM + d;
        size_t io = (size_t)i * DIM + d;

        float cu = user_emb[uo];  // u always < N_USERS
        float ci = item_emb[(size_t)(i - N_USERS) * DIM + d];

        float lu = (cu + 3.0f * g_E1[uo] + 2.0f * g_E2[uo] + g_E3[uo]) * 0.25f;
        float li = (ci + 3.0f * g_E1[io] + 2.0f * g_E2[io] + g_E3[io]) * 0.25f;
        s = fmaf(lu, li, s);
    }
#pragma unroll
    for (int o = 16; o > 0; o >>= 1)
        s += __shfl_xor_sync(0xffffffffu, s, o);
    if (lane == 0) out[b] = s;
}

// ---------------------------------------------------------------------------
// kernel_launch — stream-ordered, graph-capturable, allocation-free.
// Inputs: users, items, rows, cols, vals, user_emb, item_emb, user_emb0, item_emb0
// ---------------------------------------------------------------------------
extern "C" void kernel_launch(void* const* d_in, const int* in_sizes, int n_in,
                              void* d_out, int out_size)
{
    const int*   users     = (const int*)  d_in[0];
    const int*   items     = (const int*)  d_in[1];
    const int*   rows      = (const int*)  d_in[2];
    const int*   cols      = (const int*)  d_in[3];
    const float* vals      = (const float*)d_in[4];
    const float* user_emb  = (const float*)d_in[5];
    const float* item_emb  = (const float*)d_in[6];
    const float* user_emb0 = (const float*)d_in[7];
    const float* item_emb0 = (const float*)d_in[8];
    float*       out       = (float*)d_out;

    const int nnz = in_sizes[2];
    const int B   = in_sizes[0];

    // --- CSR build + flag propagation ---
    k_zero<<<(N_NODES + 255) / 256, 256>>>();
    k_mark_queries<<<(B + 255) / 256, 256>>>(users, items, B);
    k_hist<<<(nnz + 255) / 256, 256>>>(rows, nnz);
    k_scan_sums<<<SCAN_NBLK, SCAN_THREADS>>>();
    k_scan_top<<<1, 256>>>(nnz);
    k_scan_final<<<SCAN_NBLK, SCAN_THREADS>>>();
    k_scatter<<<(nnz + 255) / 256, 256>>>(rows, cols, vals, nnz);

    // --- 3 propagation layers (warp per row, pruned by output sparsity) ---
    int spmm_blocks = (N_NODES + 7) / 8;
    k_spmm_csr<0><<<spmm_blocks, 256>>>((const float2*)user_emb,
                                        (const float2*)item_emb,
                                        (const float2*)user_emb0,
                                        (const float2*)item_emb0);
    k_spmm_csr<1><<<spmm_blocks, 256>>>((const float2*)user_emb,
                                        (const float2*)item_emb,
                                        (const float2*)user_emb0,
                                        (const float2*)item_emb0);
    k_spmm_csr<2><<<spmm_blocks, 256>>>((const float2*)user_emb,
                                        (const float2*)item_emb,
                                        (const float2*)user_emb0,
                                        (const float2*)item_emb0);

    // --- readout ---
    k_epilogue<<<(B * 32 + 255) / 256, 256>>>(users, items, user_emb, item_emb,
                                              out, B);
}

// round 8
// speedup vs baseline: 3.0278x; 1.0152x over previous
#include <cuda_runtime.h>
#include <cstdint>

// ---------------------------------------------------------------------------
// VS_LightGCN: 3-layer LightGCN propagation + dot-product readout.
//   N = 300000, D = 64, NNZ = 5e6, ALPHA = 0.5
//   Ek = SpMM(A, E_{k-1}) + 0.5*emb0     (E0 = cat(user_emb, item_emb))
//   light = (E0 + 3E1 + 2E2 + E3)/4 ;  gamma[b] = <light[u], light[N_USERS+i]>
//
// R8: R7 with the legal form of the L2 evict_last hint
// (createpolicy + ld.global.nc.L2::cache_hint — direct qualifier is 256b-only
// on sm_103a ptxas).
// ---------------------------------------------------------------------------

#define N_USERS 100000
#define N_ITEMS 200000
#define N_NODES (N_USERS + N_ITEMS)
#define DIM     64
#define DIM2    32           // float2 chunks per row
#define NNZ_MAX 5000000
#define MAX_Q   8192         // max unique query rows (2*B)

#define SCAN_THREADS 512
#define SCAN_ITEMS   4
#define SCAN_CHUNK   (SCAN_THREADS * SCAN_ITEMS)                // 2048
#define SCAN_NBLK    ((N_NODES + SCAN_CHUNK - 1) / SCAN_CHUNK)  // 147

// ---- static device scratch (no allocations allowed) -----------------------
__device__ float g_E1[(size_t)N_NODES * DIM];
__device__ float g_E2[(size_t)N_NODES * DIM];
__device__ float g_E3[(size_t)N_NODES * DIM];
__device__ int   g_cnt[N_NODES];
__device__ int   g_rowptr[N_NODES + 1];
__device__ int   g_cursor[N_NODES];
__device__ int   g_bsum[SCAN_NBLK];
__device__ int   g_bbase[SCAN_NBLK];
__device__ int2  g_edge[NNZ_MAX];          // packed {col, bits(val)}
__device__ unsigned char g_flag2[N_NODES]; // E2 rows needed downstream
__device__ int   g_flag3[N_NODES];         // E3 rows needed (int for atomicExch)
__device__ int   g_work3[MAX_Q];           // compact list of E3 rows
__device__ int   g_nwork3;

// ---------------------------------------------------------------------------
// L2 evict_last access policy + hinted gather (keep tables resident in L2)
// ---------------------------------------------------------------------------
__device__ __forceinline__ uint64_t mk_policy()
{
    uint64_t pol;
    asm("createpolicy.fractional.L2::evict_last.b64 %0, 1.0;" : "=l"(pol));
    return pol;
}

__device__ __forceinline__ float2 ld_el(const float2* p, uint64_t pol)
{
    float2 g;
    asm("ld.global.nc.L2::cache_hint.v2.f32 {%0,%1},[%2],%3;"
        : "=f"(g.x), "=f"(g.y) : "l"(p), "l"(pol));
    return g;
}

// ---------------------------------------------------------------------------
// 1) zero counts + flags + worklist counter
// ---------------------------------------------------------------------------
__global__ void k_zero()
{
    int i = blockIdx.x * blockDim.x + threadIdx.x;
    if (i < N_NODES) {
        g_cnt[i]   = 0;
        g_flag2[i] = 0;
        g_flag3[i] = 0;
    }
    if (i == 0) g_nwork3 = 0;
}

// ---------------------------------------------------------------------------
// 1b) mark query nodes: flag3 + dedup worklist; flag2 (E2 read at queries too)
// ---------------------------------------------------------------------------
__global__ void k_mark_queries(const int* __restrict__ users,
                               const int* __restrict__ items, int B)
{
    int b = blockIdx.x * blockDim.x + threadIdx.x;
    if (b >= B) return;
    int u = users[b];
    int i = N_USERS + items[b];
    g_flag2[u] = 1;
    g_flag2[i] = 1;
    if (atomicExch(&g_flag3[u], 1) == 0) {
        int p = atomicAdd(&g_nwork3, 1);
        g_work3[p] = u;
    }
    if (atomicExch(&g_flag3[i], 1) == 0) {
        int p = atomicAdd(&g_nwork3, 1);
        g_work3[p] = i;
    }
}

// ---------------------------------------------------------------------------
// 2) histogram of destination rows (4 edges/thread, int4 loads)
// ---------------------------------------------------------------------------
__global__ void k_hist(const int* __restrict__ rows, int nnz)
{
    int t = blockIdx.x * blockDim.x + threadIdx.x;
    int e0 = t * 4;
    if (e0 + 3 < nnz) {
        int4 r = __ldg((const int4*)(rows + e0));
        atomicAdd(&g_cnt[r.x], 1);
        atomicAdd(&g_cnt[r.y], 1);
        atomicAdd(&g_cnt[r.z], 1);
        atomicAdd(&g_cnt[r.w], 1);
    } else {
        for (int e = e0; e < nnz; e++) atomicAdd(&g_cnt[rows[e]], 1);
    }
}

// ---------------------------------------------------------------------------
// 3a) per-block sums of counts
// ---------------------------------------------------------------------------
__global__ void k_scan_sums()
{
    __shared__ int warp_sums[SCAN_THREADS / 32];
    int i0 = blockIdx.x * SCAN_CHUNK + threadIdx.x * SCAN_ITEMS;
    int t = 0;
#pragma unroll
    for (int k = 0; k < SCAN_ITEMS; k++) {
        int i = i0 + k;
        t += (i < N_NODES) ? g_cnt[i] : 0;
    }
#pragma unroll
    for (int o = 16; o > 0; o >>= 1) t += __shfl_xor_sync(0xffffffffu, t, o);
    int lane = threadIdx.x & 31, wid = threadIdx.x >> 5;
    if (lane == 0) warp_sums[wid] = t;
    __syncthreads();
    if (threadIdx.x == 0) {
        int s = 0;
#pragma unroll
        for (int w = 0; w < SCAN_THREADS / 32; w++) s += warp_sums[w];
        g_bsum[blockIdx.x] = s;
    }
}

// ---------------------------------------------------------------------------
// 3b) parallel scan over the 147 block sums
// ---------------------------------------------------------------------------
__global__ void k_scan_top(int nnz)
{
    __shared__ int sh[256];
    int i = threadIdx.x;
    int v = (i < SCAN_NBLK) ? g_bsum[i] : 0;
    sh[i] = v;
    __syncthreads();
#pragma unroll
    for (int o = 1; o < 256; o <<= 1) {
        int t = (i >= o) ? sh[i - o] : 0;
        __syncthreads();
        sh[i] += t;
        __syncthreads();
    }
    if (i < SCAN_NBLK) g_bbase[i] = sh[i] - v;   // exclusive
    if (i == 0) g_rowptr[N_NODES] = nnz;
}

// ---------------------------------------------------------------------------
// 3c) block-local exclusive scan + base -> rowptr & cursor
// ---------------------------------------------------------------------------
__global__ void k_scan_final()
{
    __shared__ int warp_sums[SCAN_THREADS / 32];
    int lane = threadIdx.x & 31, wid = threadIdx.x >> 5;
    int i0 = blockIdx.x * SCAN_CHUNK + threadIdx.x * SCAN_ITEMS;

    int c[SCAN_ITEMS];
    int t = 0;
#pragma unroll
    for (int k = 0; k < SCAN_ITEMS; k++) {
        int i = i0 + k;
        c[k] = (i < N_NODES) ? g_cnt[i] : 0;
        t += c[k];
    }
    int incl = t;
#pragma unroll
    for (int o = 1; o < 32; o <<= 1) {
        int v = __shfl_up_sync(0xffffffffu, incl, o);
        if (lane >= o) incl += v;
    }
    if (lane == 31) warp_sums[wid] = incl;
    __syncthreads();
    if (wid == 0) {
        int v = (lane < SCAN_THREADS / 32) ? warp_sums[lane] : 0;
#pragma unroll
        for (int o = 1; o < SCAN_THREADS / 32; o <<= 1) {
            int u = __shfl_up_sync(0xffffffffu, v, o);
            if (lane >= o) v += u;
        }
        if (lane < SCAN_THREADS / 32) warp_sums[lane] = v;
    }
    __syncthreads();
    int warp_excl = (wid == 0) ? 0 : warp_sums[wid - 1];
    int ex = g_bbase[blockIdx.x] + warp_excl + (incl - t);
#pragma unroll
    for (int k = 0; k < SCAN_ITEMS; k++) {
        int i = i0 + k;
        if (i < N_NODES) {
            g_rowptr[i] = ex;
            g_cursor[i] = ex;
            ex += c[k];
        }
    }
}

// ---------------------------------------------------------------------------
// 4) scatter edges into CSR slots (4 edges/thread, vector loads)
//    + propagate flag3 -> flag2 over edges
// ---------------------------------------------------------------------------
__device__ __forceinline__ void scatter_one(int r, int c, float v)
{
    int pos = atomicAdd(&g_cursor[r], 1);
    g_edge[pos] = make_int2(c, __float_as_int(v));
    if (g_flag3[r]) g_flag2[c] = 1;
}

__global__ void k_scatter(const int*   __restrict__ rows,
                          const int*   __restrict__ cols,
                          const float* __restrict__ vals, int nnz)
{
    int t = blockIdx.x * blockDim.x + threadIdx.x;
    int e0 = t * 4;
    if (e0 + 3 < nnz) {
        int4   r = __ldg((const int4*)(rows + e0));
        int4   c = __ldg((const int4*)(cols + e0));
        float4 v = __ldg((const float4*)(vals + e0));
        scatter_one(r.x, c.x, v.x);
        scatter_one(r.y, c.y, v.y);
        scatter_one(r.z, c.z, v.z);
        scatter_one(r.w, c.w, v.w);
    } else {
        for (int e = e0; e < nnz; e++) scatter_one(rows[e], cols[e], vals[e]);
    }
}

// ---------------------------------------------------------------------------
// 5) Row-parallel SpMM: warp per row, lane owns one float2 of D.
//    2-edge unroll, dual accumulators, L2 evict_last (cache_hint) gathers.
// ---------------------------------------------------------------------------
template <int LAYER>
__device__ __forceinline__ float2 gather(int c, int lane, uint64_t pol,
                                         const float2* __restrict__ ue,
                                         const float2* __restrict__ ie)
{
    const float2* p;
    if (LAYER == 0) {
        p = (c < N_USERS) ? (ue + (size_t)c * DIM2)
                          : (ie + (size_t)(c - N_USERS) * DIM2);
    } else if (LAYER == 1) {
        p = reinterpret_cast<const float2*>(g_E1) + (size_t)c * DIM2;
    } else {
        p = reinterpret_cast<const float2*>(g_E2) + (size_t)c * DIM2;
    }
    return ld_el(p + lane, pol);
}

template <int LAYER>
__device__ __forceinline__ void spmm_row(int row, int lane,
                                         const float2* __restrict__ ue,
                                         const float2* __restrict__ ie,
                                         const float2* __restrict__ ue0,
                                         const float2* __restrict__ ie0)
{
    uint64_t pol = mk_policy();

    int start = __ldg(&g_rowptr[row]);
    int end   = __ldg(&g_rowptr[row + 1]);

    float2 r0 = (row < N_USERS) ? __ldg(&ue0[(size_t)row * DIM2 + lane])
                                : __ldg(&ie0[(size_t)(row - N_USERS) * DIM2 + lane]);
    float2 acc0 = make_float2(0.5f * r0.x, 0.5f * r0.y);
    float2 acc1 = make_float2(0.0f, 0.0f);

    int j = start;
    for (; j + 2 <= end; j += 2) {
        int2 e0 = __ldg(&g_edge[j]);
        int2 e1 = __ldg(&g_edge[j + 1]);
        float2 g0 = gather<LAYER>(e0.x, lane, pol, ue, ie);
        float2 g1 = gather<LAYER>(e1.x, lane, pol, ue, ie);
        float v0 = __int_as_float(e0.y);
        float v1 = __int_as_float(e1.y);
        acc0.x = fmaf(v0, g0.x, acc0.x);
        acc0.y = fmaf(v0, g0.y, acc0.y);
        acc1.x = fmaf(v1, g1.x, acc1.x);
        acc1.y = fmaf(v1, g1.y, acc1.y);
    }
    if (j < end) {
        int2 e0 = __ldg(&g_edge[j]);
        float2 g0 = gather<LAYER>(e0.x, lane, pol, ue, ie);
        float v0 = __int_as_float(e0.y);
        acc0.x = fmaf(v0, g0.x, acc0.x);
        acc0.y = fmaf(v0, g0.y, acc0.y);
    }
    acc0.x += acc1.x;
    acc0.y += acc1.y;

    float2* out = reinterpret_cast<float2*>(
        (LAYER == 0) ? g_E1 : (LAYER == 1) ? g_E2 : g_E3);
    out[(size_t)row * DIM2 + lane] = acc0;
}

template <int LAYER>
__global__ void __launch_bounds__(256)
k_spmm_csr(const float2* __restrict__ ue,  const float2* __restrict__ ie,
           const float2* __restrict__ ue0, const float2* __restrict__ ie0)
{
    int w    = (blockIdx.x * blockDim.x + threadIdx.x) >> 5;
    int lane = threadIdx.x & 31;
    if (w >= N_NODES) return;
    if (LAYER == 1 && !g_flag2[w]) return;
    spmm_row<LAYER>(w, lane, ue, ie, ue0, ie0);
}

// Layer 2 over the compact worklist (<= MAX_Q rows)
__global__ void __launch_bounds__(256)
k_spmm_l3(const float2* __restrict__ ue,  const float2* __restrict__ ie,
          const float2* __restrict__ ue0, const float2* __restrict__ ie0)
{
    int w    = (blockIdx.x * blockDim.x + threadIdx.x) >> 5;
    int lane = threadIdx.x & 31;
    if (w >= g_nwork3) return;
    int row = g_work3[w];
    spmm_row<2>(row, lane, ue, ie, ue0, ie0);
}

// ---------------------------------------------------------------------------
// 6) Epilogue: warp per output b.
// ---------------------------------------------------------------------------
__global__ void k_epilogue(const int* __restrict__ users,
                           const int* __restrict__ items,
                           const float* __restrict__ user_emb,
                           const float* __restrict__ item_emb,
                           float* __restrict__ out, int B)
{
    int t = blockIdx.x * blockDim.x + threadIdx.x;
    int b = t >> 5;
    int lane = t & 31;
    if (b >= B) return;

    int u = __ldg(users + b);
    int i = N_USERS + __ldg(items + b);

    float s = 0.0f;
#pragma unroll
    for (int k = 0; k < 2; k++) {
        int d = lane + 32 * k;
        size_t uo = (size_t)u * DIM + d;
        size_t io = (size_t)i * DIM + d;

        float cu = user_emb[uo];  // u always < N_USERS
        float ci = item_emb[(size_t)(i - N_USERS) * DIM + d];

        float lu = (cu + 3.0f * g_E1[uo] + 2.0f * g_E2[uo] + g_E3[uo]) * 0.25f;
        float li = (ci + 3.0f * g_E1[io] + 2.0f * g_E2[io] + g_E3[io]) * 0.25f;
        s = fmaf(lu, li, s);
    }
#pragma unroll
    for (int o = 16; o > 0; o >>= 1)
        s += __shfl_xor_sync(0xffffffffu, s, o);
    if (lane == 0) out[b] = s;
}

// ---------------------------------------------------------------------------
// kernel_launch — stream-ordered, graph-capturable, allocation-free.
// Inputs: users, items, rows, cols, vals, user_emb, item_emb, user_emb0, item_emb0
// ---------------------------------------------------------------------------
extern "C" void kernel_launch(void* const* d_in, const int* in_sizes, int n_in,
                              void* d_out, int out_size)
{
    const int*   users     = (const int*)  d_in[0];
    const int*   items     = (const int*)  d_in[1];
    const int*   rows      = (const int*)  d_in[2];
    const int*   cols      = (const int*)  d_in[3];
    const float* vals      = (const float*)d_in[4];
    const float* user_emb  = (const float*)d_in[5];
    const float* item_emb  = (const float*)d_in[6];
    const float* user_emb0 = (const float*)d_in[7];
    const float* item_emb0 = (const float*)d_in[8];
    float*       out       = (float*)d_out;

    const int nnz = in_sizes[2];
    const int B   = in_sizes[0];

    // --- CSR build + flag propagation ---
    k_zero<<<(N_NODES + 255) / 256, 256>>>();
    k_mark_queries<<<(B + 255) / 256, 256>>>(users, items, B);
    {
        int nt4 = (nnz + 3) / 4;
        k_hist<<<(nt4 + 255) / 256, 256>>>(rows, nnz);
    }
    k_scan_sums<<<SCAN_NBLK, SCAN_THREADS>>>();
    k_scan_top<<<1, 256>>>(nnz);
    k_scan_final<<<SCAN_NBLK, SCAN_THREADS>>>();
    {
        int nt4 = (nnz + 3) / 4;
        k_scatter<<<(nt4 + 255) / 256, 256>>>(rows, cols, vals, nnz);
    }

    // --- 3 propagation layers ---
    int spmm_blocks = (N_NODES + 7) / 8;
    k_spmm_csr<0><<<spmm_blocks, 256>>>((const float2*)user_emb,
                                        (const float2*)item_emb,
                                        (const float2*)user_emb0,
                                        (const float2*)item_emb0);
    k_spmm_csr<1><<<spmm_blocks, 256>>>((const float2*)user_emb,
                                        (const float2*)item_emb,
                                        (const float2*)user_emb0,
                                        (const float2*)item_emb0);
    k_spmm_l3<<<(MAX_Q * 32 + 255) / 256, 256>>>((const float2*)user_emb,
                                                 (const float2*)item_emb,
                                                 (const float2*)user_emb0,
                                                 (const float2*)item_emb0);

    // --- readout ---
    k_epilogue<<<(B * 32 + 255) / 256, 256>>>(users, items, user_emb, item_emb,
                                              out, B);
}

// round 9
// speedup vs baseline: 3.5269x; 1.1649x over previous
#include <cuda_runtime.h>
#include <cuda_fp16.h>
#include <cstdint>

// ---------------------------------------------------------------------------
// VS_LightGCN: 3-layer LightGCN propagation + dot-product readout.
//   N = 300000, D = 64, NNZ = 5e6, ALPHA = 0.5
//   Ek = SpMM(A, E_{k-1}) + 0.5*emb0     (E0 = cat(user_emb, item_emb))
//   light = (E0 + 3E1 + 2E2 + E3)/4 ;  gamma[b] = <light[u], light[N_USERS+i]>
//
// R9: fp16 storage for all gathered operands (fp32 accumulation). Halves the
// SpMM gather bytes — the measured bottleneck (LTS byte throughput).
// ---------------------------------------------------------------------------

#define N_USERS 100000
#define N_ITEMS 200000
#define N_NODES (N_USERS + N_ITEMS)
#define DIM     64
#define DIMH2   32           // half2 chunks per row
#define NNZ_MAX 5000000
#define MAX_Q   8192         // max unique query rows (2*B)

#define SCAN_THREADS 512
#define SCAN_ITEMS   4
#define SCAN_CHUNK   (SCAN_THREADS * SCAN_ITEMS)                // 2048
#define SCAN_NBLK    ((N_NODES + SCAN_CHUNK - 1) / SCAN_CHUNK)  // 147

// ---- static device scratch (no allocations allowed) -----------------------
__device__ __half g_H0[(size_t)N_NODES * DIM];   // fp16 concat(E0)
__device__ __half g_H1[(size_t)N_NODES * DIM];   // fp16 E1
__device__ __half g_H2[(size_t)N_NODES * DIM];   // fp16 E2
__device__ __half g_H3[(size_t)N_NODES * DIM];   // fp16 E3
__device__ int   g_cnt[N_NODES];
__device__ int   g_rowptr[N_NODES + 1];
__device__ int   g_cursor[N_NODES];
__device__ int   g_bsum[SCAN_NBLK];
__device__ int   g_bbase[SCAN_NBLK];
__device__ int2  g_edge[NNZ_MAX];          // packed {col, bits(val)}
__device__ unsigned char g_flag2[N_NODES]; // E2 rows needed downstream
__device__ int   g_flag3[N_NODES];         // E3 rows needed (int for atomicExch)
__device__ int   g_work3[MAX_Q];           // compact list of E3 rows
__device__ int   g_nwork3;

// ---------------------------------------------------------------------------
// 0) convert fp32 concat(user_emb,item_emb) -> fp16 g_H0
// ---------------------------------------------------------------------------
__global__ void k_convert(const float2* __restrict__ ue,
                          const float2* __restrict__ ie)
{
    int j = blockIdx.x * blockDim.x + threadIdx.x;    // half2 chunk index
    const int total = N_NODES * DIMH2;
    if (j >= total) return;
    int n = j >> 5;                                    // node (DIMH2 == 32)
    float2 v = (n < N_USERS) ? __ldg(&ue[j])
                             : __ldg(&ie[j - N_USERS * DIMH2]);
    reinterpret_cast<__half2*>(g_H0)[j] = __float22half2_rn(v);
}

// ---------------------------------------------------------------------------
// 1) zero counts + flags + worklist counter
// ---------------------------------------------------------------------------
__global__ void k_zero()
{
    int i = blockIdx.x * blockDim.x + threadIdx.x;
    if (i < N_NODES) {
        g_cnt[i]   = 0;
        g_flag2[i] = 0;
        g_flag3[i] = 0;
    }
    if (i == 0) g_nwork3 = 0;
}

// ---------------------------------------------------------------------------
// 1b) mark query nodes: flag3 + dedup worklist; flag2 (E2 read at queries too)
// ---------------------------------------------------------------------------
__global__ void k_mark_queries(const int* __restrict__ users,
                               const int* __restrict__ items, int B)
{
    int b = blockIdx.x * blockDim.x + threadIdx.x;
    if (b >= B) return;
    int u = users[b];
    int i = N_USERS + items[b];
    g_flag2[u] = 1;
    g_flag2[i] = 1;
    if (atomicExch(&g_flag3[u], 1) == 0) {
        int p = atomicAdd(&g_nwork3, 1);
        g_work3[p] = u;
    }
    if (atomicExch(&g_flag3[i], 1) == 0) {
        int p = atomicAdd(&g_nwork3, 1);
        g_work3[p] = i;
    }
}

// ---------------------------------------------------------------------------
// 2) histogram of destination rows (4 edges/thread, int4 loads)
// ---------------------------------------------------------------------------
__global__ void k_hist(const int* __restrict__ rows, int nnz)
{
    int t = blockIdx.x * blockDim.x + threadIdx.x;
    int e0 = t * 4;
    if (e0 + 3 < nnz) {
        int4 r = __ldg((const int4*)(rows + e0));
        atomicAdd(&g_cnt[r.x], 1);
        atomicAdd(&g_cnt[r.y], 1);
        atomicAdd(&g_cnt[r.z], 1);
        atomicAdd(&g_cnt[r.w], 1);
    } else {
        for (int e = e0; e < nnz; e++) atomicAdd(&g_cnt[rows[e]], 1);
    }
}

// ---------------------------------------------------------------------------
// 3a) per-block sums of counts
// ---------------------------------------------------------------------------
__global__ void k_scan_sums()
{
    __shared__ int warp_sums[SCAN_THREADS / 32];
    int i0 = blockIdx.x * SCAN_CHUNK + threadIdx.x * SCAN_ITEMS;
    int t = 0;
#pragma unroll
    for (int k = 0; k < SCAN_ITEMS; k++) {
        int i = i0 + k;
        t += (i < N_NODES) ? g_cnt[i] : 0;
    }
#pragma unroll
    for (int o = 16; o > 0; o >>= 1) t += __shfl_xor_sync(0xffffffffu, t, o);
    int lane = threadIdx.x & 31, wid = threadIdx.x >> 5;
    if (lane == 0) warp_sums[wid] = t;
    __syncthreads();
    if (threadIdx.x == 0) {
        int s = 0;
#pragma unroll
        for (int w = 0; w < SCAN_THREADS / 32; w++) s += warp_sums[w];
        g_bsum[blockIdx.x] = s;
    }
}

// ---------------------------------------------------------------------------
// 3b) parallel scan over the 147 block sums
// ---------------------------------------------------------------------------
__global__ void k_scan_top(int nnz)
{
    __shared__ int sh[256];
    int i = threadIdx.x;
    int v = (i < SCAN_NBLK) ? g_bsum[i] : 0;
    sh[i] = v;
    __syncthreads();
#pragma unroll
    for (int o = 1; o < 256; o <<= 1) {
        int t = (i >= o) ? sh[i - o] : 0;
        __syncthreads();
        sh[i] += t;
        __syncthreads();
    }
    if (i < SCAN_NBLK) g_bbase[i] = sh[i] - v;   // exclusive
    if (i == 0) g_rowptr[N_NODES] = nnz;
}

// ---------------------------------------------------------------------------
// 3c) block-local exclusive scan + base -> rowptr & cursor
// ---------------------------------------------------------------------------
__global__ void k_scan_final()
{
    __shared__ int warp_sums[SCAN_THREADS / 32];
    int lane = threadIdx.x & 31, wid = threadIdx.x >> 5;
    int i0 = blockIdx.x * SCAN_CHUNK + threadIdx.x * SCAN_ITEMS;

    int c[SCAN_ITEMS];
    int t = 0;
#pragma unroll
    for (int k = 0; k < SCAN_ITEMS; k++) {
        int i = i0 + k;
        c[k] = (i < N_NODES) ? g_cnt[i] : 0;
        t += c[k];
    }
    int incl = t;
#pragma unroll
    for (int o = 1; o < 32; o <<= 1) {
        int v = __shfl_up_sync(0xffffffffu, incl, o);
        if (lane >= o) incl += v;
    }
    if (lane == 31) warp_sums[wid] = incl;
    __syncthreads();
    if (wid == 0) {
        int v = (lane < SCAN_THREADS / 32) ? warp_sums[lane] : 0;
#pragma unroll
        for (int o = 1; o < SCAN_THREADS / 32; o <<= 1) {
            int u = __shfl_up_sync(0xffffffffu, v, o);
            if (lane >= o) v += u;
        }
        if (lane < SCAN_THREADS / 32) warp_sums[lane] = v;
    }
    __syncthreads();
    int warp_excl = (wid == 0) ? 0 : warp_sums[wid - 1];
    int ex = g_bbase[blockIdx.x] + warp_excl + (incl - t);
#pragma unroll
    for (int k = 0; k < SCAN_ITEMS; k++) {
        int i = i0 + k;
        if (i < N_NODES) {
            g_rowptr[i] = ex;
            g_cursor[i] = ex;
            ex += c[k];
        }
    }
}

// ---------------------------------------------------------------------------
// 4) scatter edges into CSR slots (4 edges/thread, vector loads)
//    + propagate flag3 -> flag2 over edges
// ---------------------------------------------------------------------------
__device__ __forceinline__ void scatter_one(int r, int c, float v)
{
    int pos = atomicAdd(&g_cursor[r], 1);
    g_edge[pos] = make_int2(c, __float_as_int(v));
    if (g_flag3[r]) g_flag2[c] = 1;
}

__global__ void k_scatter(const int*   __restrict__ rows,
                          const int*   __restrict__ cols,
                          const float* __restrict__ vals, int nnz)
{
    int t = blockIdx.x * blockDim.x + threadIdx.x;
    int e0 = t * 4;
    if (e0 + 3 < nnz) {
        int4   r = __ldg((const int4*)(rows + e0));
        int4   c = __ldg((const int4*)(cols + e0));
        float4 v = __ldg((const float4*)(vals + e0));
        scatter_one(r.x, c.x, v.x);
        scatter_one(r.y, c.y, v.y);
        scatter_one(r.z, c.z, v.z);
        scatter_one(r.w, c.w, v.w);
    } else {
        for (int e = e0; e < nnz; e++) scatter_one(rows[e], cols[e], vals[e]);
    }
}

// ---------------------------------------------------------------------------
// 5) Row-parallel SpMM: warp per row, lane owns one half2 (2 dims) of D.
//    fp16 gather, fp32 accumulate, fp16 store. 2-edge unroll.
//    LAYER: 0 reads g_H0 -> g_H1, 1 reads g_H1 -> g_H2, 2 reads g_H2 -> g_H3.
// ---------------------------------------------------------------------------
template <int LAYER>
__device__ __forceinline__ void spmm_row(int row, int lane,
                                         const float2* __restrict__ ue0,
                                         const float2* __restrict__ ie0)
{
    const __half2* in = reinterpret_cast<const __half2*>(
        (LAYER == 0) ? g_H0 : (LAYER == 1) ? g_H1 : g_H2);

    int start = __ldg(&g_rowptr[row]);
    int end   = __ldg(&g_rowptr[row + 1]);

    float2 r0 = (row < N_USERS)
        ? __ldg(&ue0[(size_t)row * DIMH2 + lane])
        : __ldg(&ie0[(size_t)(row - N_USERS) * DIMH2 + lane]);
    float2 acc0 = make_float2(0.5f * r0.x, 0.5f * r0.y);
    float2 acc1 = make_float2(0.0f, 0.0f);

    int j = start;
    for (; j + 2 <= end; j += 2) {
        int2 e0 = __ldg(&g_edge[j]);
        int2 e1 = __ldg(&g_edge[j + 1]);
        float2 g0 = __half22float2(__ldg(in + (size_t)e0.x * DIMH2 + lane));
        float2 g1 = __half22float2(__ldg(in + (size_t)e1.x * DIMH2 + lane));
        float v0 = __int_as_float(e0.y);
        float v1 = __int_as_float(e1.y);
        acc0.x = fmaf(v0, g0.x, acc0.x);
        acc0.y = fmaf(v0, g0.y, acc0.y);
        acc1.x = fmaf(v1, g1.x, acc1.x);
        acc1.y = fmaf(v1, g1.y, acc1.y);
    }
    if (j < end) {
        int2 e0 = __ldg(&g_edge[j]);
        float2 g0 = __half22float2(__ldg(in + (size_t)e0.x * DIMH2 + lane));
        float v0 = __int_as_float(e0.y);
        acc0.x = fmaf(v0, g0.x, acc0.x);
        acc0.y = fmaf(v0, g0.y, acc0.y);
    }
    acc0.x += acc1.x;
    acc0.y += acc1.y;

    __half2* out = reinterpret_cast<__half2*>(
        (LAYER == 0) ? g_H1 : (LAYER == 1) ? g_H2 : g_H3);
    out[(size_t)row * DIMH2 + lane] = __float22half2_rn(acc0);
}

template <int LAYER>
__global__ void __launch_bounds__(256)
k_spmm_csr(const float2* __restrict__ ue0, const float2* __restrict__ ie0)
{
    int w    = (blockIdx.x * blockDim.x + threadIdx.x) >> 5;
    int lane = threadIdx.x & 31;
    if (w >= N_NODES) return;
    if (LAYER == 1 && !g_flag2[w]) return;
    spmm_row<LAYER>(w, lane, ue0, ie0);
}

// Layer 2 over the compact worklist (<= MAX_Q rows)
__global__ void __launch_bounds__(256)
k_spmm_l3(const float2* __restrict__ ue0, const float2* __restrict__ ie0)
{
    int w    = (blockIdx.x * blockDim.x + threadIdx.x) >> 5;
    int lane = threadIdx.x & 31;
    if (w >= g_nwork3) return;
    int row = g_work3[w];
    spmm_row<2>(row, lane, ue0, ie0);
}

// ---------------------------------------------------------------------------
// 6) Epilogue: warp per output b. E0 read fp32 (exact), E1..E3 fp16.
// ---------------------------------------------------------------------------
__global__ void k_epilogue(const int* __restrict__ users,
                           const int* __restrict__ items,
                           const float* __restrict__ user_emb,
                           const float* __restrict__ item_emb,
                           float* __restrict__ out, int B)
{
    int t = blockIdx.x * blockDim.x + threadIdx.x;
    int b = t >> 5;
    int lane = t & 31;
    if (b >= B) return;

    int u = __ldg(users + b);
    int i = N_USERS + __ldg(items + b);

    float s = 0.0f;
#pragma unroll
    for (int k = 0; k < 2; k++) {
        int d = lane + 32 * k;
        size_t uo = (size_t)u * DIM + d;
        size_t io = (size_t)i * DIM + d;

        float cu = user_emb[uo];  // u always < N_USERS
        float ci = item_emb[(size_t)(i - N_USERS) * DIM + d];

        float lu = (cu + 3.0f * __half2float(g_H1[uo])
                       + 2.0f * __half2float(g_H2[uo])
                       +        __half2float(g_H3[uo])) * 0.25f;
        float li = (ci + 3.0f * __half2float(g_H1[io])
                       + 2.0f * __half2float(g_H2[io])
                       +        __half2float(g_H3[io])) * 0.25f;
        s = fmaf(lu, li, s);
    }
#pragma unroll
    for (int o = 16; o > 0; o >>= 1)
        s += __shfl_xor_sync(0xffffffffu, s, o);
    if (lane == 0) out[b] = s;
}

// ---------------------------------------------------------------------------
// kernel_launch — stream-ordered, graph-capturable, allocation-free.
// Inputs: users, items, rows, cols, vals, user_emb, item_emb, user_emb0, item_emb0
// ---------------------------------------------------------------------------
extern "C" void kernel_launch(void* const* d_in, const int* in_sizes, int n_in,
                              void* d_out, int out_size)
{
    const int*   users     = (const int*)  d_in[0];
    const int*   items     = (const int*)  d_in[1];
    const int*   rows      = (const int*)  d_in[2];
    const int*   cols      = (const int*)  d_in[3];
    const float* vals      = (const float*)d_in[4];
    const float* user_emb  = (const float*)d_in[5];
    const float* item_emb  = (const float*)d_in[6];
    const float* user_emb0 = (const float*)d_in[7];
    const float* item_emb0 = (const float*)d_in[8];
    float*       out       = (float*)d_out;

    const int nnz = in_sizes[2];
    const int B   = in_sizes[0];

    // --- convert E0 to fp16 + CSR build + flag propagation ---
    {
        int total = N_NODES * DIMH2;
        k_convert<<<(total + 255) / 256, 256>>>((const float2*)user_emb,
                                                (const float2*)item_emb);
    }
    k_zero<<<(N_NODES + 255) / 256, 256>>>();
    k_mark_queries<<<(B + 255) / 256, 256>>>(users, items, B);
    {
        int nt4 = (nnz + 3) / 4;
        k_hist<<<(nt4 + 255) / 256, 256>>>(rows, nnz);
    }
    k_scan_sums<<<SCAN_NBLK, SCAN_THREADS>>>();
    k_scan_top<<<1, 256>>>(nnz);
    k_scan_final<<<SCAN_NBLK, SCAN_THREADS>>>();
    {
        int nt4 = (nnz + 3) / 4;
        k_scatter<<<(nt4 + 255) / 256, 256>>>(rows, cols, vals, nnz);
    }

    // --- 3 propagation layers ---
    int spmm_blocks = (N_NODES + 7) / 8;
    k_spmm_csr<0><<<spmm_blocks, 256>>>((const float2*)user_emb0,
                                        (const float2*)item_emb0);
    k_spmm_csr<1><<<spmm_blocks, 256>>>((const float2*)user_emb0,
                                        (const float2*)item_emb0);
    k_spmm_l3<<<(MAX_Q * 32 + 255) / 256, 256>>>((const float2*)user_emb0,
                                                 (const float2*)item_emb0);

    // --- readout ---
    k_epilogue<<<(B * 32 + 255) / 256, 256>>>(users, items, user_emb, item_emb,
                                              out, B);
}